// round 9
// baseline (speedup 1.0000x reference)
#include <cuda_runtime.h>
#include <math.h>

// Problem constants (fixed by the dataset)
#define NM 100000
#define EM 1600000
#define DD 64

// Static device scratch (no allocations allowed anywhere)
__device__ int    g_is32;       // 1 if edge_index buffer is int32-laid-out, 0 if int64
__device__ int    g_cnt[NM];
__device__ int    g_rows[EM];
__device__ int    g_cols[EM];
__device__ float  g_dinv[NM];
__device__ float2 g_u0[NM];
__device__ float2 g_y0[NM];
__device__ float2 g_u1[NM];
__device__ float2 g_y1[NM];

// K0: zero counters, accumulators, and the dtype flag
__global__ void k_zero(int n) {
    int i = blockIdx.x * blockDim.x + threadIdx.x;
    if (i == 0) g_is32 = 0;
    if (i < n) {
        g_cnt[i] = 0;
        g_y0[i] = make_float2(0.f, 0.f);
        g_y1[i] = make_float2(0.f, 0.f);
    }
}

// K1: detect buffer layout. If the buffer is int64 (little-endian, values < 2^31),
// every odd int32 word is zero. If int32, odd words are node indices (~never all 0).
// Samples 4096 words — always within bounds for either layout (>= 3.2M int32s).
__global__ void k_detect(const int* __restrict__ ei32) {
    int i = blockIdx.x * blockDim.x + threadIdx.x;   // 4096 threads
    if (ei32[2 * i + 1] != 0) atomicOr(&g_is32, 1);
}

// K2: decode edges -> int32 row/col arrays, count in-degree at targets
__global__ void k_count(const int* __restrict__ ei32, int e) {
    int i = blockIdx.x * blockDim.x + threadIdx.x;
    if (i < e) {
        int r, c;
        if (g_is32) { r = ei32[i];         c = ei32[e + i]; }
        else        { r = ei32[2 * i];     c = ei32[2 * e + 2 * i]; }
        g_rows[i] = r;
        g_cols[i] = c;
        atomicAdd(&g_cnt[c], 1);
    }
}

// K3: dinv = rsqrt(in_deg + 1)   (self-loop guarantees deg > 0)
__global__ void k_dinv(int n) {
    int i = blockIdx.x * blockDim.x + threadIdx.x;
    if (i < n) g_dinv[i] = rsqrtf((float)g_cnt[i] + 1.0f);
}

// K4: project x[N,64] by W[2,64], pre-scale by dinv: u0 = dinv * (x @ W^T)
// warp-per-node -> fully coalesced 256B row loads
__global__ void k_proj(const float* __restrict__ x, const float* __restrict__ W, int n) {
    int warp = (blockIdx.x * blockDim.x + threadIdx.x) >> 5;
    int lane = threadIdx.x & 31;
    if (warp >= n) return;
    float2 xv  = __ldg(((const float2*)x) + (size_t)warp * 32 + lane);
    float  w00 = __ldg(W + 2 * lane);
    float  w01 = __ldg(W + 2 * lane + 1);
    float  w10 = __ldg(W + DD + 2 * lane);
    float  w11 = __ldg(W + DD + 2 * lane + 1);
    float p0 = xv.x * w00 + xv.y * w01;
    float p1 = xv.x * w10 + xv.y * w11;
    #pragma unroll
    for (int o = 16; o; o >>= 1) {
        p0 += __shfl_down_sync(0xffffffffu, p0, o);
        p1 += __shfl_down_sync(0xffffffffu, p1, o);
    }
    if (lane == 0) {
        float d = g_dinv[warp];
        g_u0[warp] = make_float2(d * p0, d * p1);
    }
}

// K5 / K7: edge-parallel scatter-add of u[src] into y[dst].
// Globals selected INSIDE device code (passing __device__ symbols from host is invalid).
__global__ void k_hop_edges(int hop, int e) {
    const float2* __restrict__ u = hop ? g_u1 : g_u0;
    float2*                    y = hop ? g_y1 : g_y0;
    int i = blockIdx.x * blockDim.x + threadIdx.x;
    if (i < e) {
        int s = g_rows[i];
        int t = g_cols[i];
        float2 uv = u[s];
        atomicAdd(&y[t].x, uv.x);
        atomicAdd(&y[t].y, uv.y);
    }
}

// K6: finish hop 1: u1 = dinv^2 * (y0 + u0)  (self-loop term + norm folded for next hop)
__global__ void k_hop_finish(int n) {
    int i = blockIdx.x * blockDim.x + threadIdx.x;
    if (i < n) {
        float d  = g_dinv[i];
        float2 a = g_y0[i];
        float2 b = g_u0[i];
        float dd = d * d;
        g_u1[i] = make_float2(dd * (a.x + b.x), dd * (a.y + b.y));
    }
}

// K8: finish hop 2 + bias + log_softmax -> out[N,2]
__global__ void k_final(const float* __restrict__ bias, float* __restrict__ out, int n) {
    int i = blockIdx.x * blockDim.x + threadIdx.x;
    if (i < n) {
        float d  = g_dinv[i];
        float2 a = g_y1[i];
        float2 b = g_u1[i];
        float l0 = d * (a.x + b.x) + bias[0];
        float l1 = d * (a.y + b.y) + bias[1];
        float m   = fmaxf(l0, l1);
        float lse = m + logf(expf(l0 - m) + expf(l1 - m));
        out[2 * i]     = l0 - lse;
        out[2 * i + 1] = l1 - lse;
    }
}

extern "C" void kernel_launch(void* const* d_in, const int* in_sizes, int n_in,
                              void* d_out, int out_size) {
    const float* x    = (const float*)d_in[0];
    const int*   ei32 = (const int*)d_in[1];   // layout auto-detected on device
    const float* W    = (const float*)d_in[2];
    const float* b    = (const float*)d_in[3];
    float*       out  = (float*)d_out;

    int n = in_sizes[0] / DD;   // 100000
    int e = in_sizes[1] / 2;    // 1600000 (elem count / 2 for either dtype)
    if (n > NM) n = NM;
    if (e > EM) e = EM;

    const int B = 256;
    int gn = (n + B - 1) / B;
    int ge = (e + B - 1) / B;
    int gw = ((n * 32) + B - 1) / B;   // warp-per-node

    k_zero      <<<gn, B>>>(n);
    k_detect    <<<16, B>>>(ei32);       // 4096 sample words
    k_count     <<<ge, B>>>(ei32, e);
    k_dinv      <<<gn, B>>>(n);
    k_proj      <<<gw, B>>>(x, W, n);
    k_hop_edges <<<ge, B>>>(0, e);
    k_hop_finish<<<gn, B>>>(n);
    k_hop_edges <<<ge, B>>>(1, e);
    k_final     <<<gn, B>>>(b, out, n);
}